// round 5
// baseline (speedup 1.0000x reference)
#include <cuda_runtime.h>
#include <cuda_bf16.h>
#include <cstdint>

// Per-edge dot product: score[e] = dot(h[src[e]], h[dst[e]]), D=64.
// Warp-per-edge: lane l loads float2 #l of each 64-float row (256B coalesced
// per row per warp), FMA, butterfly-reduce, lane 0 writes.
//
// NOTE: indices are int32 on device (JAX x64 disabled downcasts the declared
// int64 to int32) — reading as int64 was R1's illegal-access bug.

#define D_FEAT 64

__global__ __launch_bounds__(256)
void u_dot_v_kernel(const float* __restrict__ h,
                    const int* __restrict__ src,
                    const int* __restrict__ dst,
                    float* __restrict__ out,
                    int n_edges)
{
    const int warp_in_block = threadIdx.x >> 5;
    const int lane = threadIdx.x & 31;
    const int e = blockIdx.x * (blockDim.x >> 5) + warp_in_block;
    if (e >= n_edges) return;

    // Warp-uniform index loads (broadcast in LSU)
    const int s = src[e];
    const int d = dst[e];

    const float2* __restrict__ rs =
        reinterpret_cast<const float2*>(h + (long long)s * D_FEAT);
    const float2* __restrict__ rd =
        reinterpret_cast<const float2*>(h + (long long)d * D_FEAT);

    const float2 a = rs[lane];
    const float2 b = rd[lane];

    float v = a.x * b.x + a.y * b.y;

    // Butterfly reduction over 32 lanes
    v += __shfl_xor_sync(0xFFFFFFFFu, v, 16);
    v += __shfl_xor_sync(0xFFFFFFFFu, v, 8);
    v += __shfl_xor_sync(0xFFFFFFFFu, v, 4);
    v += __shfl_xor_sync(0xFFFFFFFFu, v, 2);
    v += __shfl_xor_sync(0xFFFFFFFFu, v, 1);

    if (lane == 0) out[e] = v;
}

extern "C" void kernel_launch(void* const* d_in, const int* in_sizes, int n_in,
                              void* d_out, int out_size)
{
    const float* h   = (const float*)d_in[0];
    const int*   src = (const int*)d_in[1];
    const int*   dst = (const int*)d_in[2];
    float*       out = (float*)d_out;

    const int n_edges = in_sizes[1];          // E = number of src indices
    const int warps_per_block = 256 / 32;     // 8
    const int blocks = (n_edges + warps_per_block - 1) / warps_per_block;

    u_dot_v_kernel<<<blocks, 256>>>(h, src, dst, out, n_edges);
}

// round 6
// speedup vs baseline: 2.4974x; 2.4974x over previous
#include <cuda_runtime.h>
#include <cuda_bf16.h>
#include <cstdint>

// Per-edge dot product: score[e] = dot(h[src[e]], h[dst[e]]), D=64.
//
// Half-warp-per-edge, 4 edges per half (8 per warp):
//  - lane sub (0..15) of half g loads float4 #sub of each row (16x16B = 256B,
//    one LDG.128 instruction gathers two rows = two edges across the warp)
//  - indices loaded as one int4 per half (e0 multiple of 4 -> 16B aligned)
//  - 8 independent gather LDG.128 in flight per warp (vs 2 before)
//  - 4-stage butterfly within the 16-lane half (half-local mask)
//  - results packed into float4, one STG.128 per half

#define D_FEAT 64

__device__ __forceinline__ float dot4(float4 a, float4 b) {
    return a.x * b.x + a.y * b.y + a.z * b.z + a.w * b.w;
}

__device__ __forceinline__ float hreduce16(float v, unsigned hmask) {
    v += __shfl_xor_sync(hmask, v, 8);
    v += __shfl_xor_sync(hmask, v, 4);
    v += __shfl_xor_sync(hmask, v, 2);
    v += __shfl_xor_sync(hmask, v, 1);
    return v;
}

__global__ __launch_bounds__(256)
void u_dot_v_kernel(const float* __restrict__ h,
                    const int* __restrict__ src,
                    const int* __restrict__ dst,
                    float* __restrict__ out,
                    int n_edges)
{
    const int warp = threadIdx.x >> 5;
    const int lane = threadIdx.x & 31;
    const int g    = lane >> 4;      // half id (0/1)
    const int sub  = lane & 15;      // lane within half
    const unsigned hmask = 0xFFFFu << (g << 4);

    // Each warp covers 8 edges; each half covers 4 consecutive edges.
    const int e0 = (blockIdx.x * 8 + warp) * 8 + g * 4;
    if (e0 >= n_edges) return;

    if (e0 + 3 < n_edges) {
        // ---- fast path: 4 edges per half, fully vectorized ----
        const int4 sv = *reinterpret_cast<const int4*>(src + e0);
        const int4 dv = *reinterpret_cast<const int4*>(dst + e0);

        const float4* __restrict__ h4 = reinterpret_cast<const float4*>(h);

        // 8 independent gathers, all issued before any math
        const float4 a0 = h4[(long long)sv.x * (D_FEAT / 4) + sub];
        const float4 a1 = h4[(long long)sv.y * (D_FEAT / 4) + sub];
        const float4 a2 = h4[(long long)sv.z * (D_FEAT / 4) + sub];
        const float4 a3 = h4[(long long)sv.w * (D_FEAT / 4) + sub];
        const float4 b0 = h4[(long long)dv.x * (D_FEAT / 4) + sub];
        const float4 b1 = h4[(long long)dv.y * (D_FEAT / 4) + sub];
        const float4 b2 = h4[(long long)dv.z * (D_FEAT / 4) + sub];
        const float4 b3 = h4[(long long)dv.w * (D_FEAT / 4) + sub];

        float v0 = dot4(a0, b0);
        float v1 = dot4(a1, b1);
        float v2 = dot4(a2, b2);
        float v3 = dot4(a3, b3);

        // Independent 4-stage butterflies (pipelined, half-local)
        v0 = hreduce16(v0, hmask);
        v1 = hreduce16(v1, hmask);
        v2 = hreduce16(v2, hmask);
        v3 = hreduce16(v3, hmask);

        if (sub == 0) {
            float4 r = make_float4(v0, v1, v2, v3);
            *reinterpret_cast<float4*>(out + e0) = r;  // e0 % 4 == 0 -> aligned
        }
    } else {
        // ---- tail path: per-edge, guarded ----
        const float4* __restrict__ h4 = reinterpret_cast<const float4*>(h);
        for (int i = 0; i < 4; i++) {
            const int e = e0 + i;
            if (e >= n_edges) break;
            const int s = src[e];
            const int d = dst[e];
            const float4 a = h4[(long long)s * (D_FEAT / 4) + sub];
            const float4 b = h4[(long long)d * (D_FEAT / 4) + sub];
            float v = hreduce16(dot4(a, b), hmask);
            if (sub == 0) out[e] = v;
        }
    }
}

extern "C" void kernel_launch(void* const* d_in, const int* in_sizes, int n_in,
                              void* d_out, int out_size)
{
    const float* h   = (const float*)d_in[0];
    const int*   src = (const int*)d_in[1];
    const int*   dst = (const int*)d_in[2];
    float*       out = (float*)d_out;

    const int n_edges = in_sizes[1];
    const int edges_per_block = 8 * 8;   // 8 warps x 8 edges
    const int blocks = (n_edges + edges_per_block - 1) / edges_per_block;

    u_dot_v_kernel<<<blocks, 256>>>(h, src, dst, out, n_edges);
}

// round 7
// speedup vs baseline: 2.6048x; 1.0430x over previous
#include <cuda_runtime.h>
#include <cuda_bf16.h>
#include <cstdint>

// Per-edge dot product: score[e] = dot(h[src[e]], h[dst[e]]), D=64.
//
// Half-warp-per-edge, 8 edges per half (16 per warp), two 4-edge batches:
//  - lane sub (0..15) of half g loads float4 #sub of each row (16x16B = 256B;
//    one LDG.128 instruction gathers two rows = two edges across the warp)
//  - 16 independent gather LDG.128 in flight per warp
//  - indices via int4 broadcast loads, outputs via STG.128 per 4 edges
//  - 32-bit row offsets (h is 25.6MB -> fits u32 element offsets)

#define D_FEAT 64

__device__ __forceinline__ float dot4(float4 a, float4 b) {
    return a.x * b.x + a.y * b.y + a.z * b.z + a.w * b.w;
}

__device__ __forceinline__ float hreduce16(float v, unsigned hmask) {
    v += __shfl_xor_sync(hmask, v, 8);
    v += __shfl_xor_sync(hmask, v, 4);
    v += __shfl_xor_sync(hmask, v, 2);
    v += __shfl_xor_sync(hmask, v, 1);
    return v;
}

__global__ __launch_bounds__(256)
void u_dot_v_kernel(const float* __restrict__ h,
                    const int* __restrict__ src,
                    const int* __restrict__ dst,
                    float* __restrict__ out,
                    int n_edges)
{
    const int warp = threadIdx.x >> 5;
    const int lane = threadIdx.x & 31;
    const int g    = lane >> 4;      // half id (0/1)
    const unsigned sub = lane & 15;  // lane within half
    const unsigned hmask = 0xFFFFu << (g << 4);

    const float4* __restrict__ h4 = reinterpret_cast<const float4*>(h);

    // Each warp covers 16 edges; each half covers 8 consecutive edges.
    const int e0 = (blockIdx.x * 8 + warp) * 16 + g * 8;
    if (e0 >= n_edges) return;

    if (e0 + 7 < n_edges) {
        // ---- fast path: 8 edges per half, two vectorized batches ----
        const int4 s0 = *reinterpret_cast<const int4*>(src + e0);
        const int4 s1 = *reinterpret_cast<const int4*>(src + e0 + 4);
        const int4 d0 = *reinterpret_cast<const int4*>(dst + e0);
        const int4 d1 = *reinterpret_cast<const int4*>(dst + e0 + 4);

        // 16 independent gathers (u32 element offsets: idx*16 + sub)
        const float4 a0 = h4[(unsigned)s0.x * (D_FEAT / 4) + sub];
        const float4 a1 = h4[(unsigned)s0.y * (D_FEAT / 4) + sub];
        const float4 a2 = h4[(unsigned)s0.z * (D_FEAT / 4) + sub];
        const float4 a3 = h4[(unsigned)s0.w * (D_FEAT / 4) + sub];
        const float4 b0 = h4[(unsigned)d0.x * (D_FEAT / 4) + sub];
        const float4 b1 = h4[(unsigned)d0.y * (D_FEAT / 4) + sub];
        const float4 b2 = h4[(unsigned)d0.z * (D_FEAT / 4) + sub];
        const float4 b3 = h4[(unsigned)d0.w * (D_FEAT / 4) + sub];

        const float4 a4 = h4[(unsigned)s1.x * (D_FEAT / 4) + sub];
        const float4 a5 = h4[(unsigned)s1.y * (D_FEAT / 4) + sub];
        const float4 a6 = h4[(unsigned)s1.z * (D_FEAT / 4) + sub];
        const float4 a7 = h4[(unsigned)s1.w * (D_FEAT / 4) + sub];
        const float4 b4 = h4[(unsigned)d1.x * (D_FEAT / 4) + sub];
        const float4 b5 = h4[(unsigned)d1.y * (D_FEAT / 4) + sub];
        const float4 b6 = h4[(unsigned)d1.z * (D_FEAT / 4) + sub];
        const float4 b7 = h4[(unsigned)d1.w * (D_FEAT / 4) + sub];

        float v0 = dot4(a0, b0);
        float v1 = dot4(a1, b1);
        float v2 = dot4(a2, b2);
        float v3 = dot4(a3, b3);
        v0 = hreduce16(v0, hmask);
        v1 = hreduce16(v1, hmask);
        v2 = hreduce16(v2, hmask);
        v3 = hreduce16(v3, hmask);
        if (sub == 0) {
            *reinterpret_cast<float4*>(out + e0) = make_float4(v0, v1, v2, v3);
        }

        float v4 = dot4(a4, b4);
        float v5 = dot4(a5, b5);
        float v6 = dot4(a6, b6);
        float v7 = dot4(a7, b7);
        v4 = hreduce16(v4, hmask);
        v5 = hreduce16(v5, hmask);
        v6 = hreduce16(v6, hmask);
        v7 = hreduce16(v7, hmask);
        if (sub == 0) {
            *reinterpret_cast<float4*>(out + e0 + 4) = make_float4(v4, v5, v6, v7);
        }
    } else {
        // ---- tail path: per-edge, guarded ----
        for (int i = 0; i < 8; i++) {
            const int e = e0 + i;
            if (e >= n_edges) break;
            const unsigned s = (unsigned)src[e];
            const unsigned d = (unsigned)dst[e];
            const float4 a = h4[s * (D_FEAT / 4) + sub];
            const float4 b = h4[d * (D_FEAT / 4) + sub];
            float v = hreduce16(dot4(a, b), hmask);
            if (sub == 0) out[e] = v;
        }
    }
}

extern "C" void kernel_launch(void* const* d_in, const int* in_sizes, int n_in,
                              void* d_out, int out_size)
{
    const float* h   = (const float*)d_in[0];
    const int*   src = (const int*)d_in[1];
    const int*   dst = (const int*)d_in[2];
    float*       out = (float*)d_out;

    const int n_edges = in_sizes[1];
    const int edges_per_block = 8 * 16;  // 8 warps x 16 edges
    const int blocks = (n_edges + edges_per_block - 1) / edges_per_block;

    u_dot_v_kernel<<<blocks, 256>>>(h, src, dst, out, n_edges);
}

// round 8
// speedup vs baseline: 2.8542x; 1.0957x over previous
#include <cuda_runtime.h>
#include <cuda_bf16.h>
#include <cstdint>

// Per-edge dot product: score[e] = dot(h[src[e]], h[dst[e]]), D=64.
//
// 8-lanes-per-edge (4 edges per warp-pass, 2 passes = 8 edges/warp):
//  - lane sub (0..7) of group grp loads float4 #sub and #(sub+8) of each row:
//    8 lanes x 16B = 128B = exactly 1 cache line per LDG.128 per row,
//    so each warp LDG touches 4 rows x 1 line = 4 wavefronts (minimal).
//  - per edge: 1 LDG instr, 2 FFMA-quad instrs, 0.75 SHFL, vs R6's 1/4/2.
//  - all 8 gather pairs (16 LDG.128) issued before any math (MLP).

#define ROWF4 16  // 64 floats = 16 float4 per row

__device__ __forceinline__ float dot4(float4 a, float4 b) {
    return a.x * b.x + a.y * b.y + a.z * b.z + a.w * b.w;
}

__global__ __launch_bounds__(256)
void u_dot_v_kernel(const float* __restrict__ h,
                    const int* __restrict__ src,
                    const int* __restrict__ dst,
                    float* __restrict__ out,
                    int n_edges)
{
    const int warp = threadIdx.x >> 5;
    const int lane = threadIdx.x & 31;
    const int grp  = lane >> 3;          // edge group within warp (0..3)
    const unsigned sub = lane & 7;       // lane within group
    const unsigned gmask = 0xFFu << (grp << 3);

    const float4* __restrict__ h4 = reinterpret_cast<const float4*>(h);

    // 8 edges per warp: pass p handles edge e_base + p*4 + grp
    const int e_base = (blockIdx.x * 8 + warp) * 8;
    if (e_base >= n_edges) return;

    const int eA = e_base + grp;         // pass 0
    const int eB = e_base + 4 + grp;     // pass 1

    if (e_base + 7 < n_edges) {
        // ---- fast path ----
        const unsigned sA = (unsigned)src[eA];
        const unsigned dA = (unsigned)dst[eA];
        const unsigned sB = (unsigned)src[eB];
        const unsigned dB = (unsigned)dst[eB];

        // 8 independent 128B-line gathers in flight
        const float4 a0 = h4[sA * ROWF4 + sub];
        const float4 a1 = h4[sA * ROWF4 + 8 + sub];
        const float4 b0 = h4[dA * ROWF4 + sub];
        const float4 b1 = h4[dA * ROWF4 + 8 + sub];
        const float4 c0 = h4[sB * ROWF4 + sub];
        const float4 c1 = h4[sB * ROWF4 + 8 + sub];
        const float4 d0 = h4[dB * ROWF4 + sub];
        const float4 d1 = h4[dB * ROWF4 + 8 + sub];

        float vA = dot4(a0, b0) + dot4(a1, b1);
        float vB = dot4(c0, d0) + dot4(c1, d1);

        // 3-stage butterfly within each 8-lane group (4 edges per instr)
        vA += __shfl_xor_sync(gmask, vA, 4);
        vB += __shfl_xor_sync(gmask, vB, 4);
        vA += __shfl_xor_sync(gmask, vA, 2);
        vB += __shfl_xor_sync(gmask, vB, 2);
        vA += __shfl_xor_sync(gmask, vA, 1);
        vB += __shfl_xor_sync(gmask, vB, 1);

        if (sub == 0) {
            out[eA] = vA;
            out[eB] = vB;
        }
    } else {
        // ---- tail path: guarded per pass ----
        const int nm1 = n_edges - 1;
        const int eAc = eA <= nm1 ? eA : nm1;
        const int eBc = eB <= nm1 ? eB : nm1;

        const unsigned sA = (unsigned)src[eAc];
        const unsigned dA = (unsigned)dst[eAc];
        const unsigned sB = (unsigned)src[eBc];
        const unsigned dB = (unsigned)dst[eBc];

        const float4 a0 = h4[sA * ROWF4 + sub];
        const float4 a1 = h4[sA * ROWF4 + 8 + sub];
        const float4 b0 = h4[dA * ROWF4 + sub];
        const float4 b1 = h4[dA * ROWF4 + 8 + sub];
        const float4 c0 = h4[sB * ROWF4 + sub];
        const float4 c1 = h4[sB * ROWF4 + 8 + sub];
        const float4 d0 = h4[dB * ROWF4 + sub];
        const float4 d1 = h4[dB * ROWF4 + 8 + sub];

        float vA = dot4(a0, b0) + dot4(a1, b1);
        float vB = dot4(c0, d0) + dot4(c1, d1);

        vA += __shfl_xor_sync(gmask, vA, 4);
        vB += __shfl_xor_sync(gmask, vB, 4);
        vA += __shfl_xor_sync(gmask, vA, 2);
        vB += __shfl_xor_sync(gmask, vB, 2);
        vA += __shfl_xor_sync(gmask, vA, 1);
        vB += __shfl_xor_sync(gmask, vB, 1);

        if (sub == 0) {
            if (eA < n_edges) out[eA] = vA;
            if (eB < n_edges) out[eB] = vB;
        }
    }
}

extern "C" void kernel_launch(void* const* d_in, const int* in_sizes, int n_in,
                              void* d_out, int out_size)
{
    const float* h   = (const float*)d_in[0];
    const int*   src = (const int*)d_in[1];
    const int*   dst = (const int*)d_in[2];
    float*       out = (float*)d_out;

    const int n_edges = in_sizes[1];
    const int edges_per_block = 8 * 8;   // 8 warps x 8 edges
    const int blocks = (n_edges + edges_per_block - 1) / edges_per_block;

    u_dot_v_kernel<<<blocks, 256>>>(h, src, dst, out, n_edges);
}